// round 2
// baseline (speedup 1.0000x reference)
#include <cuda_runtime.h>
#include <cuda_bf16.h>

// Problem constants
#define BATCH   8192
#define INF     1024      // IN_FEATURES
#define LEAFW   256       // LEAF_WIDTH
#define OUTF    1024      // OUT_FEATURES
#define NLEAF   16
#define NNODE   15
#define ACOLS   4096      // NLEAF * LEAFW
#define APITCH  4128      // ACOLS + 16 (mixture cols) + 16 (zero pad) -> K for GEMM2

// Scratch (device globals: allocation-free rule)
__device__ float g_logits[BATCH * 16];
__device__ float g_mix[BATCH * 16];
__device__ float g_A[(size_t)BATCH * APITCH];   // scaled hidden activations + mixture cols

__device__ __forceinline__ float to_tf32(float x) {
    unsigned u;
    asm("cvt.rna.tf32.f32 %0, %1;" : "=r"(u) : "f"(x));
    return __uint_as_float(u);
}

__device__ __forceinline__ void mma_tf32(float c[4], const unsigned a[4], const unsigned b[2]) {
    asm volatile(
        "mma.sync.aligned.m16n8k8.row.col.f32.tf32.tf32.f32 "
        "{%0,%1,%2,%3}, {%4,%5,%6,%7}, {%8,%9}, {%0,%1,%2,%3};\n"
        : "+f"(c[0]), "+f"(c[1]), "+f"(c[2]), "+f"(c[3])
        : "r"(a[0]), "r"(a[1]), "r"(a[2]), "r"(a[3]),
          "r"(b[0]), "r"(b[1]));
}

// ---------------------------------------------------------------------------
// Kernel 1: node logits [BATCH,16] (col 15 = 0).  logit = x . w_node + b_node
// Block: 256 threads handle 128 rows x 16 node-slots, K tiled by 32.
// ---------------------------------------------------------------------------
__global__ void k_logits(const float* __restrict__ x,
                         const float* __restrict__ nw,
                         const float* __restrict__ nb) {
    __shared__ float xs[128][33];
    __shared__ float ws[16][33];
    const int tid  = threadIdx.x;
    const int row0 = blockIdx.x * 128;
    const int node = tid & 15;
    const int rg   = tid >> 4;          // 0..15

    float acc[8];
#pragma unroll
    for (int j = 0; j < 8; j++) acc[j] = 0.f;

    for (int k0 = 0; k0 < INF; k0 += 32) {
#pragma unroll
        for (int i = 0; i < 16; i++) {
            int idx = tid + 256 * i;            // 0..4095
            int r = idx >> 5, c = idx & 31;
            xs[r][c] = x[(size_t)(row0 + r) * INF + k0 + c];
        }
        for (int idx = tid; idx < 512; idx += 256) {
            int r = idx >> 5, c = idx & 31;
            ws[r][c] = (r < NNODE) ? nw[(size_t)r * INF + k0 + c] : 0.f;
        }
        __syncthreads();
#pragma unroll
        for (int k = 0; k < 32; k++) {
            float wv = ws[node][k];
#pragma unroll
            for (int j = 0; j < 8; j++)
                acc[j] += xs[rg + 16 * j][k] * wv;
        }
        __syncthreads();
    }
    float bias = (node < NNODE) ? nb[node] : 0.f;
#pragma unroll
    for (int j = 0; j < 8; j++)
        g_logits[(size_t)(row0 + rg + 16 * j) * 16 + node] = acc[j] + bias;
}

// ---------------------------------------------------------------------------
// Kernel 2: mixture[b,l] = prod_d s_d,  also writes mixture into g_A cols
// 4096..4111 and zeros cols 4112..4127 (bias-fold for GEMM2).
// ---------------------------------------------------------------------------
__global__ void k_mixture() {
    int idx = blockIdx.x * 256 + threadIdx.x;   // < BATCH*16
    int b = idx >> 4, l = idx & 15;
    float m = 1.f;
#pragma unroll
    for (int d = 0; d < 4; d++) {
        int g = l >> (3 - d);
        int node = (1 << d) - 1 + (g >> 1);
        float z = g_logits[(size_t)b * 16 + node];
        float s = 1.f / (1.f + expf(-z));
        m *= (g & 1) ? s : (1.f - s);
    }
    g_mix[idx] = m;
    g_A[(size_t)b * APITCH + ACOLS + l] = m;
    if (l == 0) {
#pragma unroll
        for (int c = ACOLS + 16; c < APITCH; c++)
            g_A[(size_t)b * APITCH + c] = 0.f;
    }
}

// ---------------------------------------------------------------------------
// TF32 GEMM, 128x128x32 block tile, 8 warps (2x4), warp tile 64x32,
// mma.m16n8k8 with K-permutation (phys {2c,2c+1} <-> logical {c,c+4}).
// MODE 0: g_A[m, n] = mix[m, n>>8] * relu(x @ W1cat + b1)     K=1024
// MODE 1: out[m, n] = g_A(+mix cols) @ [W2flat ; b2s ; 0]     K=4128
// ---------------------------------------------------------------------------
template <int MODE>
__global__ __launch_bounds__(256, 2) void k_gemm(
    const float* __restrict__ Ag,     // MODE0: x        MODE1: unused (g_A)
    const float* __restrict__ Bg,     // MODE0: w1s      MODE1: w2s flat [4096,1024]
    const float* __restrict__ bias,   // MODE0: b1s flat [4096]   MODE1: b2s [16,1024]
    float* __restrict__ Cg)           // MODE0: unused (g_A)      MODE1: out
{
    constexpr int K   = (MODE == 0) ? INF : APITCH;
    constexpr int LDA = (MODE == 0) ? INF : APITCH;

    __shared__ float As[128][36];
    __shared__ float Bs[32][132];

    const int tid  = threadIdx.x;
    const int lane = tid & 31;
    const int warp = tid >> 5;
    const int wm   = (warp & 1) * 64;
    const int wn   = (warp >> 1) * 32;
    const int m0   = blockIdx.y * 128;
    const int n0   = blockIdx.x * 128;

    const float* Aptr = (MODE == 0) ? Ag : g_A;
    // MODE0: B tile lives inside one leaf; leaf & h-base constant per block.
    const float* Bp = (MODE == 0)
        ? (Bg + (size_t)(n0 >> 8) * (INF * LEAFW) + (n0 & 255))
        : Bg;

    float acc[4][4][4];
#pragma unroll
    for (int a = 0; a < 4; a++)
#pragma unroll
        for (int b = 0; b < 4; b++)
#pragma unroll
            for (int e = 0; e < 4; e++) acc[a][b][e] = 0.f;

    for (int k0 = 0; k0 < K; k0 += 32) {
        // ---- load A tile (128x32) ----
#pragma unroll
        for (int i = 0; i < 4; i++) {
            int idx = tid + 256 * i;            // 0..1023
            int r = idx >> 3;
            int q = idx & 7;
            float4 v = *(const float4*)(Aptr + (size_t)(m0 + r) * LDA + k0 + 4 * q);
            float4 w;
            w.x = to_tf32(v.x); w.y = to_tf32(v.y);
            w.z = to_tf32(v.z); w.w = to_tf32(v.w);
            *(float4*)&As[r][4 * q] = w;
        }
        // ---- load B tile (32x128) ----
#pragma unroll
        for (int i = 0; i < 4; i++) {
            int idx = tid + 256 * i;            // 0..1023
            int kr = idx >> 5;
            int q  = idx & 31;
            float4 v;
            if (MODE == 0) {
                v = *(const float4*)(Bp + (size_t)(k0 + kr) * LEAFW + 4 * q);
            } else {
                int kg = k0 + kr;
                if (kg < ACOLS)
                    v = *(const float4*)(Bg + (size_t)kg * OUTF + n0 + 4 * q);
                else if (kg < ACOLS + 16)
                    v = *(const float4*)(bias + (size_t)(kg - ACOLS) * OUTF + n0 + 4 * q);
                else
                    v = make_float4(0.f, 0.f, 0.f, 0.f);
            }
            float4 w;
            w.x = to_tf32(v.x); w.y = to_tf32(v.y);
            w.z = to_tf32(v.z); w.w = to_tf32(v.w);
            *(float4*)&Bs[kr][4 * q] = w;
        }
        __syncthreads();

        // ---- compute: 4 k-steps of 8 ----
#pragma unroll
        for (int s = 0; s < 4; s++) {
            unsigned af[4][4];
            unsigned bf[4][2];
#pragma unroll
            for (int mt = 0; mt < 4; mt++) {
                int r = wm + mt * 16 + (lane >> 2);
                float2 lo = *(const float2*)&As[r][8 * s + 2 * (lane & 3)];
                float2 hi = *(const float2*)&As[r + 8][8 * s + 2 * (lane & 3)];
                af[mt][0] = __float_as_uint(lo.x);
                af[mt][2] = __float_as_uint(lo.y);
                af[mt][1] = __float_as_uint(hi.x);
                af[mt][3] = __float_as_uint(hi.y);
            }
#pragma unroll
            for (int nt = 0; nt < 4; nt++) {
                int n = wn + nt * 8 + (lane >> 2);
                bf[nt][0] = __float_as_uint(Bs[8 * s + 2 * (lane & 3)][n]);
                bf[nt][1] = __float_as_uint(Bs[8 * s + 2 * (lane & 3) + 1][n]);
            }
#pragma unroll
            for (int mt = 0; mt < 4; mt++)
#pragma unroll
                for (int nt = 0; nt < 4; nt++)
                    mma_tf32(acc[mt][nt], af[mt], bf[nt]);
        }
        __syncthreads();
    }

    // ---- epilogue ----
    if (MODE == 0) {
        const int l = n0 >> 8;       // leaf constant per block
#pragma unroll
        for (int mt = 0; mt < 4; mt++) {
#pragma unroll
            for (int nt = 0; nt < 4; nt++) {
                int gn = n0 + wn + nt * 8 + 2 * (lane & 3);
#pragma unroll
                for (int half = 0; half < 2; half++) {
                    int gm = m0 + wm + mt * 16 + (lane >> 2) + half * 8;
                    float mx = g_mix[(size_t)gm * 16 + l];
                    float v0 = acc[mt][nt][2 * half + 0] + bias[gn];
                    float v1 = acc[mt][nt][2 * half + 1] + bias[gn + 1];
                    v0 = fmaxf(v0, 0.f) * mx;
                    v1 = fmaxf(v1, 0.f) * mx;
                    *(float2*)&g_A[(size_t)gm * APITCH + gn] = make_float2(v0, v1);
                }
            }
        }
    } else {
#pragma unroll
        for (int mt = 0; mt < 4; mt++) {
#pragma unroll
            for (int nt = 0; nt < 4; nt++) {
                int gn = n0 + wn + nt * 8 + 2 * (lane & 3);
#pragma unroll
                for (int half = 0; half < 2; half++) {
                    int gm = m0 + wm + mt * 16 + (lane >> 2) + half * 8;
                    *(float2*)&Cg[(size_t)gm * OUTF + gn] =
                        make_float2(acc[mt][nt][2 * half + 0],
                                    acc[mt][nt][2 * half + 1]);
                }
            }
        }
    }
}

// ---------------------------------------------------------------------------
extern "C" void kernel_launch(void* const* d_in, const int* in_sizes, int n_in,
                              void* d_out, int out_size) {
    const float* x   = (const float*)d_in[0];
    const float* nw  = (const float*)d_in[1];   // node_weights [15,1024]
    const float* nb  = (const float*)d_in[2];   // node_biases  [15,1]
    const float* w1s = (const float*)d_in[3];   // [16,1024,256]
    const float* b1s = (const float*)d_in[4];   // [16,256] -> flat [4096]
    const float* w2s = (const float*)d_in[5];   // [16,256,1024] -> flat [4096,1024]
    const float* b2s = (const float*)d_in[6];   // [16,1024]
    float* out = (float*)d_out;

    k_logits<<<BATCH / 128, 256>>>(x, nw, nb);
    k_mixture<<<(BATCH * 16) / 256, 256>>>();
    k_gemm<0><<<dim3(ACOLS / 128, BATCH / 128), 256>>>(x, w1s, b1s, nullptr);
    k_gemm<1><<<dim3(OUTF / 128, BATCH / 128), 256>>>(nullptr, w2s, b2s, out);
}

// round 3
// speedup vs baseline: 1.4360x; 1.4360x over previous
#include <cuda_runtime.h>
#include <cuda_bf16.h>

#define BATCH   8192
#define INF     1024
#define LEAFW   256
#define OUTF    1024
#define NLEAF   16
#define NNODE   15
#define ACOLS   4096
#define APITCH  4128      // ACOLS + 16 mixture cols + 16 zero pad

// Scratch (device globals; allocation-free rule)
__device__ float g_logits[BATCH * 16];
__device__ float g_mix[BATCH * 16];
__device__ float g_xc [(size_t)BATCH * INF];      // tf32-rounded, k-permuted x
__device__ float g_w1c[(size_t)ACOLS * INF];      // W1^T  [n=4096][k=1024], tf32, k-permuted
__device__ float g_w2c[(size_t)OUTF * APITCH];    // [W2;b2;0]^T [n=1024][k=4128], tf32, k-permuted
__device__ float g_A  [(size_t)BATCH * APITCH];   // GEMM1 out (scaled, tf32, k-permuted) + mix cols

__device__ __forceinline__ float to_tf32(float x) {
    unsigned u;
    asm("cvt.rna.tf32.f32 %0, %1;" : "=r"(u) : "f"(x));
    return __uint_as_float(u);
}
__device__ __forceinline__ unsigned fu(float x) { return __float_as_uint(x); }

// logical k -> physical k within 16-blocks (float4 groups span 2 MMA k-steps)
__device__ __forceinline__ int permk(int k) {
    return (k & ~15) | ((k & 3) << 2) | (((k >> 3) & 1) << 1) | ((k >> 2) & 1);
}

__device__ __forceinline__ void mma_tf32(float c[4], const unsigned a[4], const unsigned b[2]) {
    asm volatile(
        "mma.sync.aligned.m16n8k8.row.col.f32.tf32.tf32.f32 "
        "{%0,%1,%2,%3}, {%4,%5,%6,%7}, {%8,%9}, {%0,%1,%2,%3};\n"
        : "+f"(c[0]), "+f"(c[1]), "+f"(c[2]), "+f"(c[3])
        : "r"(a[0]), "r"(a[1]), "r"(a[2]), "r"(a[3]), "r"(b[0]), "r"(b[1]));
}

__device__ __forceinline__ void cpasync16(float* dst, const float* src) {
    unsigned d = (unsigned)__cvta_generic_to_shared(dst);
    asm volatile("cp.async.cg.shared.global [%0], [%1], 16;\n" :: "r"(d), "l"(src));
}

// ---------------------------------------------------------------------------
// Prep kernels: tf32-round + k-permute operands so GEMMs do zero conversion.
// ---------------------------------------------------------------------------
__global__ void k_cvt_x(const float* __restrict__ x) {
    int idx = blockIdx.x * 256 + threadIdx.x;       // dst float4 id
    int m = idx >> 8, g4 = idx & 255;
    int t = g4 >> 2, j = g4 & 3;
    const float* src = x + (size_t)m * INF + 16 * t + j;
    float4 v;
    v.x = to_tf32(src[0]); v.y = to_tf32(src[4]);
    v.z = to_tf32(src[8]); v.w = to_tf32(src[12]);
    *(float4*)(g_xc + (size_t)m * INF + 16 * t + 4 * j) = v;
}

__global__ void k_prep_w1(const float* __restrict__ w1s) {   // [16][1024][256] -> [n][k]
    int bid = blockIdx.x;                   // 16 leaves * 32 f-tiles * 8 h-tiles
    int l  = bid >> 8;
    int f0 = ((bid >> 3) & 31) * 32;
    int h0 = (bid & 7) * 32;
    __shared__ float ts[32][33];
    int tid = threadIdx.x;
    int fi = tid >> 3, hj = (tid & 7) * 4;
    float4 v = *(const float4*)(w1s + ((size_t)l * INF + f0 + fi) * LEAFW + h0 + hj);
    ts[hj + 0][fi] = v.x; ts[hj + 1][fi] = v.y;
    ts[hj + 2][fi] = v.z; ts[hj + 3][fi] = v.w;
    __syncthreads();
    int hi = tid >> 3, fj = (tid & 7) * 4;
    size_t drow = (size_t)(l * LEAFW + h0 + hi) * INF;
#pragma unroll
    for (int e = 0; e < 4; e++)
        g_w1c[drow + permk(f0 + fj + e)] = to_tf32(ts[hi][fj + e]);
}

__global__ void k_prep_w2(const float* __restrict__ w2s) {   // [4096 lh][1024 o] -> [o][k]
    int bid = blockIdx.x;                   // 128 k-tiles * 32 o-tiles
    int k0 = (bid >> 5) * 32;
    int o0 = (bid & 31) * 32;
    __shared__ float ts[32][33];
    int tid = threadIdx.x;
    int ki = tid >> 3, oj = (tid & 7) * 4;
    float4 v = *(const float4*)(w2s + (size_t)(k0 + ki) * OUTF + o0 + oj);
    ts[oj + 0][ki] = v.x; ts[oj + 1][ki] = v.y;
    ts[oj + 2][ki] = v.z; ts[oj + 3][ki] = v.w;
    __syncthreads();
    int oi = tid >> 3, kj = (tid & 7) * 4;
    size_t drow = (size_t)(o0 + oi) * APITCH;
#pragma unroll
    for (int e = 0; e < 4; e++)
        g_w2c[drow + permk(k0 + kj + e)] = to_tf32(ts[oi][kj + e]);
}

__global__ void k_prep_tail(const float* __restrict__ b2s) {  // bias rows + zero pad of w2c
    int idx = blockIdx.x * 256 + threadIdx.x;    // 1024 * 32
    int o = idx >> 5, c = idx & 31;
    float v = 0.f;
    if (c < 16) {
        int l = (c >> 2) | ((c & 1) << 2) | (((c >> 1) & 1) << 3);   // inverse of permk in-block
        v = to_tf32(b2s[l * OUTF + o]);
    }
    g_w2c[(size_t)o * APITCH + ACOLS + c] = v;
}

// ---------------------------------------------------------------------------
// Node logits [BATCH,16] (col 15 unused=garbage-safe 0 path)
// ---------------------------------------------------------------------------
__global__ void k_logits(const float* __restrict__ x,
                         const float* __restrict__ nw,
                         const float* __restrict__ nb) {
    __shared__ float xs[128][33];
    __shared__ float ws[16][33];
    const int tid = threadIdx.x;
    const int row0 = blockIdx.x * 128;
    const int node = tid & 15;
    const int rg = tid >> 4;
    float acc[8];
#pragma unroll
    for (int j = 0; j < 8; j++) acc[j] = 0.f;
    for (int k0 = 0; k0 < INF; k0 += 32) {
#pragma unroll
        for (int i = 0; i < 16; i++) {
            int idx = tid + 256 * i;
            int r = idx >> 5, c = idx & 31;
            xs[r][c] = x[(size_t)(row0 + r) * INF + k0 + c];
        }
        for (int idx = tid; idx < 512; idx += 256) {
            int r = idx >> 5, c = idx & 31;
            ws[r][c] = (r < NNODE) ? nw[(size_t)r * INF + k0 + c] : 0.f;
        }
        __syncthreads();
#pragma unroll
        for (int k = 0; k < 32; k++) {
            float wv = ws[node][k];
#pragma unroll
            for (int j = 0; j < 8; j++) acc[j] += xs[rg + 16 * j][k] * wv;
        }
        __syncthreads();
    }
    float bias = (node < NNODE) ? nb[node] : 0.f;
#pragma unroll
    for (int j = 0; j < 8; j++)
        g_logits[(size_t)(row0 + rg + 16 * j) * 16 + node] = acc[j] + bias;
}

// ---------------------------------------------------------------------------
// Mixture + write mixture/zero columns of g_A (k-permuted, tf32)
// ---------------------------------------------------------------------------
__global__ void k_mixture() {
    int idx = blockIdx.x * 256 + threadIdx.x;
    int b = idx >> 4, l = idx & 15;
    float m = 1.f;
#pragma unroll
    for (int d = 0; d < 4; d++) {
        int g = l >> (3 - d);
        int node = (1 << d) - 1 + (g >> 1);
        float z = g_logits[(size_t)b * 16 + node];
        float s = 1.f / (1.f + expf(-z));
        m *= (g & 1) ? s : (1.f - s);
    }
    g_mix[idx] = m;
    int pc = ((l & 3) << 2) | (((l >> 3) & 1) << 1) | ((l >> 2) & 1);
    g_A[(size_t)b * APITCH + ACOLS + pc] = to_tf32(m);
    if (l == 0) {
#pragma unroll
        for (int c = ACOLS + 16; c < APITCH; c++) g_A[(size_t)b * APITCH + c] = 0.f;
    }
}

// ---------------------------------------------------------------------------
// TF32 GEMM: C[128,128] = A[128,K] * B[128,K]^T, cp.async 2-stage pipeline.
// Both operands pre-converted/permuted. Smem tiles [128][48] (conflict-free LDS.128).
// MODE 0: g_A = tf32(mix * relu(x@W1 + b1))   K=1024
// MODE 1: out = g_A @ w2c^T                   K=4128 (bias folded into K)
// ---------------------------------------------------------------------------
#define TSZ (128 * 48)

template <int MODE>
__global__ __launch_bounds__(256, 2) void k_gemm(const float* __restrict__ bias,
                                                 float* __restrict__ Cg) {
    extern __shared__ float sm[];
    constexpr int K  = MODE ? APITCH : INF;
    constexpr int KT = K / 32;

    const int tid  = threadIdx.x;
    const int lane = tid & 31;
    const int warp = tid >> 5;
    const int wm = (warp & 1) * 64;
    const int wn = (warp >> 1) * 32;
    const int m0 = blockIdx.y * 128;
    const int n0 = blockIdx.x * 128;

    const float* Ap = (MODE ? g_A : g_xc) + (size_t)m0 * K;
    const float* Bp = (MODE ? g_w2c : g_w1c) + (size_t)n0 * K;
    float* As = sm;
    float* Bs = sm + 2 * TSZ;

    const int lr = tid >> 3;          // load row base (0..31)
    const int lq = (tid & 7) * 4;     // load col (float)

    float acc[4][4][4];
#pragma unroll
    for (int a = 0; a < 4; a++)
#pragma unroll
        for (int b = 0; b < 4; b++)
#pragma unroll
            for (int e = 0; e < 4; e++) acc[a][b][e] = 0.f;

    // prologue: stage 0
    {
        float* Ad = As; float* Bd = Bs;
#pragma unroll
        for (int i = 0; i < 4; i++) {
            int r = lr + 32 * i;
            cpasync16(Ad + r * 48 + lq, Ap + (size_t)r * K + lq);
            cpasync16(Bd + r * 48 + lq, Bp + (size_t)r * K + lq);
        }
        asm volatile("cp.async.commit_group;\n");
    }

#pragma unroll 1
    for (int kt = 0; kt < KT; kt++) {
        if (kt + 1 < KT) {
            int st = (kt + 1) & 1;
            int k0 = (kt + 1) * 32;
            float* Ad = As + st * TSZ; float* Bd = Bs + st * TSZ;
#pragma unroll
            for (int i = 0; i < 4; i++) {
                int r = lr + 32 * i;
                cpasync16(Ad + r * 48 + lq, Ap + (size_t)r * K + k0 + lq);
                cpasync16(Bd + r * 48 + lq, Bp + (size_t)r * K + k0 + lq);
            }
            asm volatile("cp.async.commit_group;\n");
            asm volatile("cp.async.wait_group 1;\n");
        } else {
            asm volatile("cp.async.wait_group 0;\n");
        }
        __syncthreads();

        const float* Ab = As + (kt & 1) * TSZ;
        const float* Bb = Bs + (kt & 1) * TSZ;
#pragma unroll
        for (int t = 0; t < 2; t++) {
            float4 alo[4], ahi[4], bb[4];
#pragma unroll
            for (int mt = 0; mt < 4; mt++) {
                int r = wm + mt * 16 + (lane >> 2);
                alo[mt] = *(const float4*)(Ab + r * 48 + 16 * t + 4 * (lane & 3));
                ahi[mt] = *(const float4*)(Ab + (r + 8) * 48 + 16 * t + 4 * (lane & 3));
            }
#pragma unroll
            for (int nt = 0; nt < 4; nt++) {
                int n = wn + nt * 8 + (lane >> 2);
                bb[nt] = *(const float4*)(Bb + n * 48 + 16 * t + 4 * (lane & 3));
            }
#pragma unroll
            for (int mt = 0; mt < 4; mt++) {
                unsigned a0[4] = {fu(alo[mt].x), fu(ahi[mt].x), fu(alo[mt].y), fu(ahi[mt].y)};
                unsigned a1[4] = {fu(alo[mt].z), fu(ahi[mt].z), fu(alo[mt].w), fu(ahi[mt].w)};
#pragma unroll
                for (int nt = 0; nt < 4; nt++) {
                    unsigned b0[2] = {fu(bb[nt].x), fu(bb[nt].y)};
                    unsigned b1[2] = {fu(bb[nt].z), fu(bb[nt].w)};
                    mma_tf32(acc[mt][nt], a0, b0);
                    mma_tf32(acc[mt][nt], a1, b1);
                }
            }
        }
        __syncthreads();
    }

    // epilogue
    if (MODE == 0) {
        const int l = n0 >> 8;   // leaf constant per block (128 | 256)
#pragma unroll
        for (int mt = 0; mt < 4; mt++) {
#pragma unroll
            for (int half = 0; half < 2; half++) {
                int gm = m0 + wm + mt * 16 + (lane >> 2) + half * 8;
                float mx = g_mix[(size_t)gm * 16 + l];
                float* arow = g_A + (size_t)gm * APITCH;
#pragma unroll
                for (int nt = 0; nt < 4; nt++) {
                    int gn = n0 + wn + nt * 8 + 2 * (lane & 3);
                    float v0 = fmaxf(acc[mt][nt][2 * half + 0] + bias[gn], 0.f) * mx;
                    float v1 = fmaxf(acc[mt][nt][2 * half + 1] + bias[gn + 1], 0.f) * mx;
                    arow[permk(gn)]     = to_tf32(v0);
                    arow[permk(gn + 1)] = to_tf32(v1);
                }
            }
        }
    } else {
#pragma unroll
        for (int mt = 0; mt < 4; mt++) {
#pragma unroll
            for (int half = 0; half < 2; half++) {
                int gm = m0 + wm + mt * 16 + (lane >> 2) + half * 8;
#pragma unroll
                for (int nt = 0; nt < 4; nt++) {
                    int gn = n0 + wn + nt * 8 + 2 * (lane & 3);
                    *(float2*)(Cg + (size_t)gm * OUTF + gn) =
                        make_float2(acc[mt][nt][2 * half + 0], acc[mt][nt][2 * half + 1]);
                }
            }
        }
    }
}

// ---------------------------------------------------------------------------
extern "C" void kernel_launch(void* const* d_in, const int* in_sizes, int n_in,
                              void* d_out, int out_size) {
    const float* x   = (const float*)d_in[0];
    const float* nw  = (const float*)d_in[1];
    const float* nb  = (const float*)d_in[2];
    const float* w1s = (const float*)d_in[3];
    const float* b1s = (const float*)d_in[4];
    const float* w2s = (const float*)d_in[5];
    const float* b2s = (const float*)d_in[6];
    float* out = (float*)d_out;

    const int SMEM = 4 * TSZ * 4;   // 96 KB
    cudaFuncSetAttribute(k_gemm<0>, cudaFuncAttributeMaxDynamicSharedMemorySize, SMEM);
    cudaFuncSetAttribute(k_gemm<1>, cudaFuncAttributeMaxDynamicSharedMemorySize, SMEM);

    k_cvt_x   <<<BATCH, 256>>>(x);
    k_prep_w1 <<<4096, 256>>>(w1s);
    k_prep_w2 <<<4096, 256>>>(w2s);
    k_prep_tail<<<128, 256>>>(b2s);
    k_logits  <<<BATCH / 128, 256>>>(x, nw, nb);
    k_mixture <<<(BATCH * 16) / 256, 256>>>();
    k_gemm<0> <<<dim3(ACOLS / 128, BATCH / 128), 256, SMEM>>>(b1s, nullptr);
    k_gemm<1> <<<dim3(OUTF / 128, BATCH / 128), 256, SMEM>>>(nullptr, out);
}